// round 13
// baseline (speedup 1.0000x reference)
#include <cuda_runtime.h>
#include <cstdint>

#define GRID_G   152
#define GG       (152 * 152)          // 23104
#define NA       3
#define NCH      10                   // 7 + 3 classes
#define NB       64
#define NPOS     (NB * NA * GG)       // 4,435,968 = 17328 * 256 exactly
#define STRIDE_F 4.0f                 // 608 / 152
#define TPB      256
#define TILE_BYTES (TPB * NCH * 4)    // 10240 B per tile (both directions)

__device__ __forceinline__ float fast_sigmoid(float v) {
    return 1.0f / (1.0f + __expf(-v));
}

__device__ __forceinline__ uint32_t smem_u32(const void* p) {
    uint32_t a;
    asm("{ .reg .u64 t; cvta.to.shared.u64 t, %1; cvt.u32.u64 %0, t; }"
        : "=r"(a) : "l"(p));
    return a;
}

__device__ __forceinline__ void bulk_ld(uint32_t dst_smem, const float* src,
                                        uint32_t bytes, uint32_t mbar)
{
    asm volatile(
        "cp.async.bulk.shared::cta.global.mbarrier::complete_tx::bytes "
        "[%0], [%1], %2, [%3];"
        :: "r"(dst_smem), "l"(src), "r"(bytes), "r"(mbar)
        : "memory");
}

__global__ void __launch_bounds__(TPB)
yolo_layer_kernel(const float* __restrict__ x, float* __restrict__ out)
{
    __shared__ __align__(16) float sin_[TPB * NCH];   // in tile: [c][256]
    __shared__ __align__(16) float sout[TPB * NCH];   // out tile: [t][10]
    __shared__ __align__(8)  uint64_t mbar;

    const int t    = threadIdx.x;
    const int base = blockIdx.x * TPB;

    const uint32_t mb = smem_u32(&mbar);

    if (t == 0)
        asm volatile("mbarrier.init.shared.b64 [%0], 1;" :: "r"(mb) : "memory");
    __syncthreads();   // barrier must be initialized before anyone waits on it

    if (t == 0) {
        asm volatile("fence.proxy.async.shared::cta;" ::: "memory");

        // This block's 256 positions span at most 2 ba segments.
        // base ≡ 0 mod 64, GG ≡ 0 mod 64 → all copies are 256B-multiples, 16B-aligned.
        const int ba0 = base / GG;
        const int s0  = base - ba0 * GG;
        const int L   = (GG - s0 < TPB) ? (GG - s0) : TPB;   // seg0 length

        asm volatile(
            "mbarrier.arrive.expect_tx.shared.b64 _, [%0], %1;"
            :: "r"(mb), "r"((uint32_t)TILE_BYTES) : "memory");

        const uint32_t sdst = smem_u32(sin_);
#pragma unroll
        for (int c = 0; c < NCH; c++) {
            const float* src0 = x + ((size_t)ba0 * NCH + c) * GG + s0;
            bulk_ld(sdst + c * (TPB * 4), src0, (uint32_t)(L * 4), mb);
            if (L < TPB) {
                const float* src1 = x + ((size_t)(ba0 + 1) * NCH + c) * GG;
                bulk_ld(sdst + c * (TPB * 4) + L * 4, src1,
                        (uint32_t)((TPB - L) * 4), mb);
            }
        }
    }

    // All threads wait for the full 10240B input tile (acquire).
    {
        uint32_t done;
        asm volatile(
            "{ .reg .pred p; "
            "mbarrier.try_wait.parity.acquire.cta.shared::cta.b64 p, [%1], 0; "
            "selp.b32 %0, 1, 0, p; }"
            : "=r"(done) : "r"(mb) : "memory");
        while (!done) {
            asm volatile(
                "{ .reg .pred p; "
                "mbarrier.try_wait.parity.acquire.cta.shared::cta.b64 p, [%1], 0, 0x989680; "
                "selp.b32 %0, 1, 0, p; }"
                : "=r"(done) : "r"(mb) : "memory");
        }
    }

    const int idx = base + t;
    const int s   = idx % GG;
    const int ba  = idx / GG;
    const int a   = ba % NA;
    const int gy  = s / GRID_G;
    const int gx  = s - gy * GRID_G;

    // conflict-free: c-stride = 256 floats ≡ 0 mod 32 banks
    const float v0 = sin_[0 * TPB + t];
    const float v1 = sin_[1 * TPB + t];
    const float v2 = sin_[2 * TPB + t];
    const float v3 = sin_[3 * TPB + t];
    const float v4 = sin_[4 * TPB + t];
    const float v5 = sin_[5 * TPB + t];
    const float v6 = sin_[6 * TPB + t];
    const float v7 = sin_[7 * TPB + t];
    const float v8 = sin_[8 * TPB + t];
    const float v9 = sin_[9 * TPB + t];

    const float aw = (a == 0) ? 11.0f : (a == 1) ? 24.0f : 42.0f;
    const float ah = (a == 0) ? 14.0f : (a == 1) ? 17.0f : 27.0f;

    float* __restrict__ row = sout + t * NCH;
    row[0] = (fast_sigmoid(v0) + (float)gx) * STRIDE_F;
    row[1] = (fast_sigmoid(v1) + (float)gy) * STRIDE_F;
    row[2] = __expf(v2) * aw;
    row[3] = __expf(v3) * ah;
    row[4] = v4;
    row[5] = v5;
    row[6] = fast_sigmoid(v6);
    row[7] = fast_sigmoid(v7);
    row[8] = fast_sigmoid(v8);
    row[9] = fast_sigmoid(v9);

    __syncthreads();

    // Single bulk TMA store of the 10240B output tile.
    if (t == 0) {
        asm volatile("fence.proxy.async.shared::cta;" ::: "memory");
        float* gdst = out + (size_t)base * NCH;
        asm volatile(
            "cp.async.bulk.global.shared::cta.bulk_group [%0], [%1], %2;"
            :: "l"(gdst), "r"(smem_u32(sout)), "r"((uint32_t)TILE_BYTES)
            : "memory");
        asm volatile("cp.async.bulk.commit_group;" ::: "memory");
        asm volatile("cp.async.bulk.wait_group 0;" ::: "memory");
    }
}

extern "C" void kernel_launch(void* const* d_in, const int* in_sizes, int n_in,
                              void* d_out, int out_size)
{
    const float* x = (const float*)d_in[0];
    float* out = (float*)d_out;

    const int blocks = NPOS / TPB;   // 17328
    yolo_layer_kernel<<<blocks, TPB>>>(x, out);
}